// round 1
// baseline (speedup 1.0000x reference)
#include <cuda_runtime.h>
#include <cstdint>

// Problem constants (from reference): N=100000, E=1600000, D=H=128, C=40
#define NMAX 100096          // 782*128, padded
#define EMAX 1600000
#define SCAN_CH 1024
#define NBMAX 128

// ---------------- scratch (device globals; no allocation allowed) -----------
__device__ int   g_cnt[NMAX];
__device__ int   g_row[NMAX + 1];
__device__ int   g_cur[NMAX];
__device__ int   g_col[EMAX];
__device__ float g_dinv[NMAX];
__device__ int   g_bsum[NBMAX];
__device__ float g_h0[(size_t)NMAX * 128];
__device__ float g_h1[(size_t)NMAX * 128];
__device__ float g_h2[(size_t)NMAX * 40];

// ---------------- CSR build --------------------------------------------------
__global__ void k_zero(int n) {
    int i = blockIdx.x * blockDim.x + threadIdx.x;
    if (i < n) g_cnt[i] = 0;
}

__global__ void k_count(const int* __restrict__ dst, int E) {
    int e = blockIdx.x * blockDim.x + threadIdx.x;
    if (e < E) atomicAdd(&g_cnt[dst[e]], 1);
}

__global__ void k_dinv(int n) {
    int i = blockIdx.x * blockDim.x + threadIdx.x;
    if (i < n) g_dinv[i] = rsqrtf((float)(g_cnt[i] + 1));  // +1 self loop
}

// per-chunk exclusive scan (chunk = 1024)
__global__ void k_scan1(int n) {
    __shared__ int s[SCAN_CH];
    int tid = threadIdx.x;
    int i = blockIdx.x * SCAN_CH + tid;
    int v = (i < n) ? g_cnt[i] : 0;
    s[tid] = v;
    __syncthreads();
    #pragma unroll
    for (int off = 1; off < SCAN_CH; off <<= 1) {
        int t = (tid >= off) ? s[tid - off] : 0;
        __syncthreads();
        s[tid] += t;
        __syncthreads();
    }
    if (i < n) g_row[i] = s[tid] - v;              // exclusive within chunk
    if (tid == SCAN_CH - 1) g_bsum[blockIdx.x] = s[tid];
}

// scan of chunk sums (nb <= 128), single block of 128 threads
__global__ void k_scan2(int nb) {
    __shared__ int s[NBMAX];
    int tid = threadIdx.x;
    int v = (tid < nb) ? g_bsum[tid] : 0;
    s[tid] = v;
    __syncthreads();
    #pragma unroll
    for (int off = 1; off < NBMAX; off <<= 1) {
        int t = (tid >= off) ? s[tid - off] : 0;
        __syncthreads();
        s[tid] += t;
        __syncthreads();
    }
    if (tid < nb) g_bsum[tid] = s[tid] - v;        // exclusive
}

__global__ void k_scan3(int n, int E) {
    int i = blockIdx.x * blockDim.x + threadIdx.x;
    if (i < n) {
        int r = g_row[i] + g_bsum[i >> 10];
        g_row[i] = r;
        g_cur[i] = r;
    }
    if (i == 0) g_row[n] = E;
}

__global__ void k_scatter(const int* __restrict__ src, const int* __restrict__ dst, int E) {
    int e = blockIdx.x * blockDim.x + threadIdx.x;
    if (e < E) {
        int d = dst[e];
        int p = atomicAdd(&g_cur[d], 1);
        g_col[p] = src[e];
    }
}

// ---------------- GEMM: [N,128] @ [128,128] ---------------------------------
// BM=128, BN=128, BK=32, 256 threads, 8x8 microtile
__global__ void __launch_bounds__(256) k_gemm128(const float* __restrict__ Xext, int inSel,
                                                 const float* __restrict__ W, int outSel, int N) {
    __shared__ float Xs[128][33];
    __shared__ float Ws[32][128];
    const float* X = Xext ? Xext : (inSel == 0 ? g_h0 : g_h1);
    float* Y = (outSel == 0) ? g_h0 : g_h1;
    int tid = threadIdx.x;
    int row0 = blockIdx.x * 128;
    int tmg = tid >> 4, tng = tid & 15;
    float acc[8][8];
    #pragma unroll
    for (int i = 0; i < 8; i++)
        #pragma unroll
        for (int j = 0; j < 8; j++) acc[i][j] = 0.f;

    for (int k0 = 0; k0 < 128; k0 += 32) {
        #pragma unroll
        for (int i = 0; i < 4; i++) {
            int idx = tid + 256 * i;            // 0..1023 float4 slots
            int r = idx >> 3, c4 = (idx & 7) << 2;
            int gr = row0 + r;
            float4 v = make_float4(0.f, 0.f, 0.f, 0.f);
            if (gr < N) v = *(const float4*)(X + (size_t)gr * 128 + k0 + c4);
            Xs[r][c4 + 0] = v.x; Xs[r][c4 + 1] = v.y;
            Xs[r][c4 + 2] = v.z; Xs[r][c4 + 3] = v.w;
        }
        #pragma unroll
        for (int i = 0; i < 4; i++) {
            int idx = tid + 256 * i;
            int r = idx >> 5, c4 = (idx & 31) << 2;
            *(float4*)&Ws[r][c4] = *(const float4*)(W + (size_t)(k0 + r) * 128 + c4);
        }
        __syncthreads();
        #pragma unroll 8
        for (int k = 0; k < 32; k++) {
            float a[8], b[8];
            #pragma unroll
            for (int i = 0; i < 8; i++) a[i] = Xs[tmg * 8 + i][k];
            #pragma unroll
            for (int j = 0; j < 8; j++) b[j] = Ws[k][tng * 8 + j];
            #pragma unroll
            for (int i = 0; i < 8; i++)
                #pragma unroll
                for (int j = 0; j < 8; j++) acc[i][j] = fmaf(a[i], b[j], acc[i][j]);
        }
        __syncthreads();
    }
    #pragma unroll
    for (int i = 0; i < 8; i++) {
        int gr = row0 + tmg * 8 + i;
        if (gr < N) {
            #pragma unroll
            for (int j = 0; j < 8; j++) Y[(size_t)gr * 128 + tng * 8 + j] = acc[i][j];
        }
    }
}

// ---------------- GEMM: [N,128] @ [128,40] (in g_h1, out g_h2) --------------
// BM=128, 128 threads, 8 rows x 5 cols microtile
__global__ void __launch_bounds__(128) k_gemm40(const float* __restrict__ W, int N) {
    __shared__ float Xs[128][33];
    __shared__ float Ws[32][40];
    int tid = threadIdx.x;
    int row0 = blockIdx.x * 128;
    int rg = tid >> 3, cg = tid & 7;   // 16 row groups x 8 col groups
    float acc[8][5];
    #pragma unroll
    for (int i = 0; i < 8; i++)
        #pragma unroll
        for (int j = 0; j < 5; j++) acc[i][j] = 0.f;

    for (int k0 = 0; k0 < 128; k0 += 32) {
        #pragma unroll
        for (int i = 0; i < 8; i++) {
            int idx = tid + 128 * i;            // 1024 float4 slots
            int r = idx >> 3, c4 = (idx & 7) << 2;
            int gr = row0 + r;
            float4 v = make_float4(0.f, 0.f, 0.f, 0.f);
            if (gr < N) v = *(const float4*)(g_h1 + (size_t)gr * 128 + k0 + c4);
            Xs[r][c4 + 0] = v.x; Xs[r][c4 + 1] = v.y;
            Xs[r][c4 + 2] = v.z; Xs[r][c4 + 3] = v.w;
        }
        #pragma unroll
        for (int i = 0; i < 10; i++) {
            int idx = tid + 128 * i;            // 1280 scalars
            int r = idx / 40, c = idx % 40;
            Ws[r][c] = W[(size_t)(k0 + r) * 40 + c];
        }
        __syncthreads();
        #pragma unroll 8
        for (int k = 0; k < 32; k++) {
            float a[8], b[5];
            #pragma unroll
            for (int i = 0; i < 8; i++) a[i] = Xs[rg * 8 + i][k];
            #pragma unroll
            for (int j = 0; j < 5; j++) b[j] = Ws[k][cg * 5 + j];
            #pragma unroll
            for (int i = 0; i < 8; i++)
                #pragma unroll
                for (int j = 0; j < 5; j++) acc[i][j] = fmaf(a[i], b[j], acc[i][j]);
        }
        __syncthreads();
    }
    #pragma unroll
    for (int i = 0; i < 8; i++) {
        int gr = row0 + rg * 8 + i;
        if (gr < N) {
            #pragma unroll
            for (int j = 0; j < 5; j++) g_h2[(size_t)gr * 40 + cg * 5 + j] = acc[i][j];
        }
    }
}

// ---------------- Aggregation (pull-CSR), 128 features, 1 warp / node -------
__global__ void __launch_bounds__(256) k_agg128(int inSel, int outSel,
                                                const float* __restrict__ bias, int relu, int n) {
    const float* t = (inSel == 0) ? g_h0 : g_h1;
    float* o = (outSel == 0) ? g_h0 : g_h1;
    int warp = (blockIdx.x * 256 + threadIdx.x) >> 5;
    int lane = threadIdx.x & 31;
    if (warp >= n) return;
    int v = warp;
    float dv = g_dinv[v];
    float4 acc = *(const float4*)(t + (size_t)v * 128 + lane * 4);   // self loop: dv * t[v]
    acc.x *= dv; acc.y *= dv; acc.z *= dv; acc.w *= dv;
    int rb = g_row[v], re = g_row[v + 1];
    for (int s0 = rb; s0 < re; s0 += 32) {
        int idx = s0 + lane;
        int u = 0; float su = 0.f;
        if (idx < re) { u = g_col[idx]; su = g_dinv[u]; }
        int cnt = min(32, re - s0);
        for (int j = 0; j < cnt; j++) {
            int uj = __shfl_sync(0xffffffffu, u, j);
            float sj = __shfl_sync(0xffffffffu, su, j);
            float4 r = *(const float4*)(t + (size_t)uj * 128 + lane * 4);
            acc.x = fmaf(sj, r.x, acc.x);
            acc.y = fmaf(sj, r.y, acc.y);
            acc.z = fmaf(sj, r.z, acc.z);
            acc.w = fmaf(sj, r.w, acc.w);
        }
    }
    float4 bv = *(const float4*)(bias + lane * 4);
    float4 out;
    out.x = fmaf(dv, acc.x, bv.x);
    out.y = fmaf(dv, acc.y, bv.y);
    out.z = fmaf(dv, acc.z, bv.z);
    out.w = fmaf(dv, acc.w, bv.w);
    if (relu) {
        out.x = fmaxf(out.x, 0.f); out.y = fmaxf(out.y, 0.f);
        out.z = fmaxf(out.z, 0.f); out.w = fmaxf(out.w, 0.f);
    }
    *(float4*)(o + (size_t)v * 128 + lane * 4) = out;
}

// ---------------- Aggregation, 40 features (in g_h2, out ext) ---------------
__global__ void __launch_bounds__(256) k_agg40(float* __restrict__ O,
                                               const float* __restrict__ bias, int n) {
    int warp = (blockIdx.x * 256 + threadIdx.x) >> 5;
    int lane = threadIdx.x & 31;
    if (warp >= n) return;
    int v = warp;
    float dv = g_dinv[v];
    bool act = lane < 10;                 // 10 * float4 = 40 features
    float4 acc = make_float4(0.f, 0.f, 0.f, 0.f);
    if (act) {
        acc = *(const float4*)(g_h2 + (size_t)v * 40 + lane * 4);
        acc.x *= dv; acc.y *= dv; acc.z *= dv; acc.w *= dv;
    }
    int rb = g_row[v], re = g_row[v + 1];
    for (int s0 = rb; s0 < re; s0 += 32) {
        int idx = s0 + lane;
        int u = 0; float su = 0.f;
        if (idx < re) { u = g_col[idx]; su = g_dinv[u]; }
        int cnt = min(32, re - s0);
        for (int j = 0; j < cnt; j++) {
            int uj = __shfl_sync(0xffffffffu, u, j);
            float sj = __shfl_sync(0xffffffffu, su, j);
            if (act) {
                float4 r = *(const float4*)(g_h2 + (size_t)uj * 40 + lane * 4);
                acc.x = fmaf(sj, r.x, acc.x);
                acc.y = fmaf(sj, r.y, acc.y);
                acc.z = fmaf(sj, r.z, acc.z);
                acc.w = fmaf(sj, r.w, acc.w);
            }
        }
    }
    if (act) {
        float4 bv = *(const float4*)(bias + lane * 4);
        float4 out;
        out.x = fmaf(dv, acc.x, bv.x);
        out.y = fmaf(dv, acc.y, bv.y);
        out.z = fmaf(dv, acc.z, bv.z);
        out.w = fmaf(dv, acc.w, bv.w);
        *(float4*)(O + (size_t)v * 40 + lane * 4) = out;
    }
}

// ---------------- launch -----------------------------------------------------
extern "C" void kernel_launch(void* const* d_in, const int* in_sizes, int n_in,
                              void* d_out, int out_size) {
    const float* x  = (const float*)d_in[0];
    const int*   ei = (const int*)d_in[1];
    const float* W0 = (const float*)d_in[2];
    const float* b0 = (const float*)d_in[3];
    const float* W1 = (const float*)d_in[4];
    const float* b1 = (const float*)d_in[5];
    const float* W2 = (const float*)d_in[6];
    const float* b2 = (const float*)d_in[7];
    float* out = (float*)d_out;

    int N = in_sizes[0] / 128;
    int E = in_sizes[1] / 2;
    const int* src = ei;
    const int* dst = ei + E;

    // --- CSR build + degrees ---
    k_zero   <<<(N + 255) / 256, 256>>>(N);
    k_count  <<<(E + 255) / 256, 256>>>(dst, E);
    k_dinv   <<<(N + 255) / 256, 256>>>(N);
    int nb = (N + SCAN_CH - 1) / SCAN_CH;
    k_scan1  <<<nb, SCAN_CH>>>(N);
    k_scan2  <<<1, NBMAX>>>(nb);
    k_scan3  <<<(N + 255) / 256, 256>>>(N, E);
    k_scatter<<<(E + 255) / 256, 256>>>(src, dst, E);

    int gb  = (N + 127) / 128;             // gemm blocks
    int ab  = (N + 7) / 8;                 // agg blocks (8 warps / block)

    // layer 0: x @ W0 -> h0 ; agg(h0) + b0, relu -> h1
    k_gemm128<<<gb, 256>>>(x, -1, W0, 0, N);
    k_agg128 <<<ab, 256>>>(0, 1, b0, 1, N);
    // layer 1: h1 @ W1 -> h0 ; agg(h0) + b1, relu -> h1
    k_gemm128<<<gb, 256>>>(nullptr, 1, W1, 0, N);
    k_agg128 <<<ab, 256>>>(0, 1, b1, 1, N);
    // layer 2: h1 @ W2 -> h2 ; agg(h2) + b2 -> out
    k_gemm40 <<<gb, 128>>>(W2, N);
    k_agg40  <<<ab, 256>>>(out, b2, N);
}

// round 4
// speedup vs baseline: 1.0730x; 1.0730x over previous
#include <cuda_runtime.h>
#include <cstdint>

// Problem constants: N=100000, E=1600000, D=H=128, C=40
#define NMAX 100096
#define EMAX 1600000
#define SCAN_CH 1024
#define NBMAX 128

// ---------------- scratch (device globals; no allocation allowed) -----------
__device__ int   g_cnt[NMAX];
__device__ int   g_row[NMAX + 1];
__device__ int   g_cur[NMAX];
__device__ int   g_col[EMAX];
__device__ float g_dinv[NMAX];
__device__ int   g_bsum[NBMAX];
__device__ float g_h0[(size_t)NMAX * 128];
__device__ float g_h1[(size_t)NMAX * 128];
__device__ float g_h2[(size_t)NMAX * 40];

// ---------------- packed f32x2 helpers ---------------------------------------
// fma.rn.f32x2: Blackwell packed fp32 FMA (2x FFMA throughput). Baseline
// sm_100+ PTX (not an 'a'-gated feature, unlike tcgen05).
#define FMA2(d, a, b, c) \
    asm("fma.rn.f32x2 %0, %1, %2, %3;" : "=l"(d) : "l"(a), "l"(b), "l"(c))
#define PACKDUP(d, s) \
    asm("mov.b64 %0, {%1, %1};" : "=l"(d) : "r"(s))

union U64F2 { unsigned long long u; float2 f; };

// ---------------- CSR build --------------------------------------------------
__global__ void k_zero(int n) {
    int i = blockIdx.x * blockDim.x + threadIdx.x;
    if (i < n) g_cnt[i] = 0;
}
__global__ void k_count(const int* __restrict__ dst, int E) {
    int e = blockIdx.x * blockDim.x + threadIdx.x;
    if (e < E) atomicAdd(&g_cnt[dst[e]], 1);
}
__global__ void k_dinv(int n) {
    int i = blockIdx.x * blockDim.x + threadIdx.x;
    if (i < n) g_dinv[i] = rsqrtf((float)(g_cnt[i] + 1));
}
__global__ void k_scan1(int n) {
    __shared__ int s[SCAN_CH];
    int tid = threadIdx.x;
    int i = blockIdx.x * SCAN_CH + tid;
    int v = (i < n) ? g_cnt[i] : 0;
    s[tid] = v;
    __syncthreads();
    #pragma unroll
    for (int off = 1; off < SCAN_CH; off <<= 1) {
        int t = (tid >= off) ? s[tid - off] : 0;
        __syncthreads();
        s[tid] += t;
        __syncthreads();
    }
    if (i < n) g_row[i] = s[tid] - v;
    if (tid == SCAN_CH - 1) g_bsum[blockIdx.x] = s[tid];
}
__global__ void k_scan2(int nb) {
    __shared__ int s[NBMAX];
    int tid = threadIdx.x;
    int v = (tid < nb) ? g_bsum[tid] : 0;
    s[tid] = v;
    __syncthreads();
    #pragma unroll
    for (int off = 1; off < NBMAX; off <<= 1) {
        int t = (tid >= off) ? s[tid - off] : 0;
        __syncthreads();
        s[tid] += t;
        __syncthreads();
    }
    if (tid < nb) g_bsum[tid] = s[tid] - v;
}
__global__ void k_scan3(int n, int E) {
    int i = blockIdx.x * blockDim.x + threadIdx.x;
    if (i < n) {
        int r = g_row[i] + g_bsum[i >> 10];
        g_row[i] = r;
        g_cur[i] = r;
    }
    if (i == 0) g_row[n] = E;
}
__global__ void k_scatter(const int* __restrict__ src, const int* __restrict__ dst, int E) {
    int e = blockIdx.x * blockDim.x + threadIdx.x;
    if (e < E) {
        int d = dst[e];
        int p = atomicAdd(&g_cur[d], 1);
        g_col[p] = src[e];
    }
}

// ---------------- GEMM: [N,128] @ [128,128], f32x2 packed FMA ----------------
// BM=128, BN=128, BK=32, 256 threads, 8 rows x 8 cols (4 packed pairs) microtile
__global__ void __launch_bounds__(256) k_gemm128(const float* __restrict__ Xext, int inSel,
                                                 const float* __restrict__ W, int outSel, int N) {
    __shared__ float Xs[128][33];
    __shared__ float Ws[32][128];
    const float* X = Xext ? Xext : (inSel == 0 ? g_h0 : g_h1);
    float* Y = (outSel == 0) ? g_h0 : g_h1;
    int tid = threadIdx.x;
    int row0 = blockIdx.x * 128;
    int tmg = tid >> 4, tng = tid & 15;
    unsigned long long acc[8][4];
    #pragma unroll
    for (int i = 0; i < 8; i++)
        #pragma unroll
        for (int j = 0; j < 4; j++) acc[i][j] = 0ull;

    for (int k0 = 0; k0 < 128; k0 += 32) {
        #pragma unroll
        for (int i = 0; i < 4; i++) {
            int idx = tid + 256 * i;            // 1024 float4 slots
            int r = idx >> 3, c4 = (idx & 7) << 2;
            int gr = row0 + r;
            float4 v = make_float4(0.f, 0.f, 0.f, 0.f);
            if (gr < N) v = *(const float4*)(X + (size_t)gr * 128 + k0 + c4);
            Xs[r][c4 + 0] = v.x; Xs[r][c4 + 1] = v.y;
            Xs[r][c4 + 2] = v.z; Xs[r][c4 + 3] = v.w;
        }
        #pragma unroll
        for (int i = 0; i < 4; i++) {
            int idx = tid + 256 * i;
            int r = idx >> 5, c4 = (idx & 31) << 2;
            *(float4*)&Ws[r][c4] = *(const float4*)(W + (size_t)(k0 + r) * 128 + c4);
        }
        __syncthreads();
        #pragma unroll 8
        for (int k = 0; k < 32; k++) {
            unsigned long long ap[8], bp[4];
            #pragma unroll
            for (int i = 0; i < 8; i++) {
                unsigned int ab = __float_as_uint(Xs[tmg * 8 + i][k]);
                PACKDUP(ap[i], ab);
            }
            #pragma unroll
            for (int j = 0; j < 4; j++)
                bp[j] = *(const unsigned long long*)&Ws[k][tng * 8 + 2 * j];
            #pragma unroll
            for (int i = 0; i < 8; i++)
                #pragma unroll
                for (int j = 0; j < 4; j++)
                    FMA2(acc[i][j], ap[i], bp[j], acc[i][j]);
        }
        __syncthreads();
    }
    #pragma unroll
    for (int i = 0; i < 8; i++) {
        int gr = row0 + tmg * 8 + i;
        if (gr < N) {
            #pragma unroll
            for (int j = 0; j < 2; j++) {
                U64F2 c0, c1;
                c0.u = acc[i][2 * j]; c1.u = acc[i][2 * j + 1];
                *(float4*)(Y + (size_t)gr * 128 + tng * 8 + 4 * j) =
                    make_float4(c0.f.x, c0.f.y, c1.f.x, c1.f.y);
            }
        }
    }
}

// ---------------- GEMM: [N,128] @ [128,40] (in g_h1, out g_h2) ---------------
__global__ void __launch_bounds__(128) k_gemm40(const float* __restrict__ W, int N) {
    __shared__ float Xs[128][33];
    __shared__ float Ws[32][40];
    int tid = threadIdx.x;
    int row0 = blockIdx.x * 128;
    int rg = tid >> 3, cg = tid & 7;
    float acc[8][5];
    #pragma unroll
    for (int i = 0; i < 8; i++)
        #pragma unroll
        for (int j = 0; j < 5; j++) acc[i][j] = 0.f;

    for (int k0 = 0; k0 < 128; k0 += 32) {
        #pragma unroll
        for (int i = 0; i < 8; i++) {
            int idx = tid + 128 * i;
            int r = idx >> 3, c4 = (idx & 7) << 2;
            int gr = row0 + r;
            float4 v = make_float4(0.f, 0.f, 0.f, 0.f);
            if (gr < N) v = *(const float4*)(g_h1 + (size_t)gr * 128 + k0 + c4);
            Xs[r][c4 + 0] = v.x; Xs[r][c4 + 1] = v.y;
            Xs[r][c4 + 2] = v.z; Xs[r][c4 + 3] = v.w;
        }
        #pragma unroll
        for (int i = 0; i < 10; i++) {
            int idx = tid + 128 * i;
            int r = idx / 40, c = idx % 40;
            Ws[r][c] = W[(size_t)(k0 + r) * 40 + c];
        }
        __syncthreads();
        #pragma unroll 8
        for (int k = 0; k < 32; k++) {
            float a[8], b[5];
            #pragma unroll
            for (int i = 0; i < 8; i++) a[i] = Xs[rg * 8 + i][k];
            #pragma unroll
            for (int j = 0; j < 5; j++) b[j] = Ws[k][cg * 5 + j];
            #pragma unroll
            for (int i = 0; i < 8; i++)
                #pragma unroll
                for (int j = 0; j < 5; j++) acc[i][j] = fmaf(a[i], b[j], acc[i][j]);
        }
        __syncthreads();
    }
    #pragma unroll
    for (int i = 0; i < 8; i++) {
        int gr = row0 + rg * 8 + i;
        if (gr < N) {
            #pragma unroll
            for (int j = 0; j < 5; j++) g_h2[(size_t)gr * 40 + cg * 5 + j] = acc[i][j];
        }
    }
}

// ---------------- Aggregation (pull-CSR), 128 features, 1 warp / node -------
// Inner loop manually unrolled x4 for MLP (4 independent LDG.128 in flight).
__global__ void __launch_bounds__(256) k_agg128(int inSel, int outSel,
                                                const float* __restrict__ bias, int relu, int n) {
    const float* __restrict__ t = (inSel == 0) ? g_h0 : g_h1;
    float* o = (outSel == 0) ? g_h0 : g_h1;
    int warp = (blockIdx.x * 256 + threadIdx.x) >> 5;
    int lane = threadIdx.x & 31;
    if (warp >= n) return;
    int v = warp;
    float dv = g_dinv[v];
    float4 acc = *(const float4*)(t + (size_t)v * 128 + lane * 4);   // self loop
    acc.x *= dv; acc.y *= dv; acc.z *= dv; acc.w *= dv;
    int rb = g_row[v], re = g_row[v + 1];
    for (int s0 = rb; s0 < re; s0 += 32) {
        int idx = s0 + lane;
        int u = 0; float su = 0.f;
        if (idx < re) { u = g_col[idx]; su = g_dinv[u]; }
        int cnt = min(32, re - s0);
        int j = 0;
        for (; j + 4 <= cnt; j += 4) {
            int u0 = __shfl_sync(0xffffffffu, u, j + 0);
            int u1 = __shfl_sync(0xffffffffu, u, j + 1);
            int u2 = __shfl_sync(0xffffffffu, u, j + 2);
            int u3 = __shfl_sync(0xffffffffu, u, j + 3);
            float c0 = __shfl_sync(0xffffffffu, su, j + 0);
            float c1 = __shfl_sync(0xffffffffu, su, j + 1);
            float c2 = __shfl_sync(0xffffffffu, su, j + 2);
            float c3 = __shfl_sync(0xffffffffu, su, j + 3);
            float4 r0 = *(const float4*)(t + (size_t)u0 * 128 + lane * 4);
            float4 r1 = *(const float4*)(t + (size_t)u1 * 128 + lane * 4);
            float4 r2 = *(const float4*)(t + (size_t)u2 * 128 + lane * 4);
            float4 r3 = *(const float4*)(t + (size_t)u3 * 128 + lane * 4);
            acc.x = fmaf(c0, r0.x, acc.x); acc.y = fmaf(c0, r0.y, acc.y);
            acc.z = fmaf(c0, r0.z, acc.z); acc.w = fmaf(c0, r0.w, acc.w);
            acc.x = fmaf(c1, r1.x, acc.x); acc.y = fmaf(c1, r1.y, acc.y);
            acc.z = fmaf(c1, r1.z, acc.z); acc.w = fmaf(c1, r1.w, acc.w);
            acc.x = fmaf(c2, r2.x, acc.x); acc.y = fmaf(c2, r2.y, acc.y);
            acc.z = fmaf(c2, r2.z, acc.z); acc.w = fmaf(c2, r2.w, acc.w);
            acc.x = fmaf(c3, r3.x, acc.x); acc.y = fmaf(c3, r3.y, acc.y);
            acc.z = fmaf(c3, r3.z, acc.z); acc.w = fmaf(c3, r3.w, acc.w);
        }
        for (; j < cnt; j++) {
            int uj = __shfl_sync(0xffffffffu, u, j);
            float sj = __shfl_sync(0xffffffffu, su, j);
            float4 r = *(const float4*)(t + (size_t)uj * 128 + lane * 4);
            acc.x = fmaf(sj, r.x, acc.x);
            acc.y = fmaf(sj, r.y, acc.y);
            acc.z = fmaf(sj, r.z, acc.z);
            acc.w = fmaf(sj, r.w, acc.w);
        }
    }
    float4 bv = *(const float4*)(bias + lane * 4);
    float4 out;
    out.x = fmaf(dv, acc.x, bv.x);
    out.y = fmaf(dv, acc.y, bv.y);
    out.z = fmaf(dv, acc.z, bv.z);
    out.w = fmaf(dv, acc.w, bv.w);
    if (relu) {
        out.x = fmaxf(out.x, 0.f); out.y = fmaxf(out.y, 0.f);
        out.z = fmaxf(out.z, 0.f); out.w = fmaxf(out.w, 0.f);
    }
    *(float4*)(o + (size_t)v * 128 + lane * 4) = out;
}

// ---------------- Aggregation, 40 features (in g_h2, out ext) ---------------
__global__ void __launch_bounds__(256) k_agg40(float* __restrict__ O,
                                               const float* __restrict__ bias, int n) {
    int warp = (blockIdx.x * 256 + threadIdx.x) >> 5;
    int lane = threadIdx.x & 31;
    if (warp >= n) return;
    int v = warp;
    float dv = g_dinv[v];
    bool act = lane < 10;
    float4 acc = make_float4(0.f, 0.f, 0.f, 0.f);
    if (act) {
        acc = *(const float4*)(g_h2 + (size_t)v * 40 + lane * 4);
        acc.x *= dv; acc.y *= dv; acc.z *= dv; acc.w *= dv;
    }
    int rb = g_row[v], re = g_row[v + 1];
    for (int s0 = rb; s0 < re; s0 += 32) {
        int idx = s0 + lane;
        int u = 0; float su = 0.f;
        if (idx < re) { u = g_col[idx]; su = g_dinv[u]; }
        int cnt = min(32, re - s0);
        int j = 0;
        for (; j + 2 <= cnt; j += 2) {
            int u0 = __shfl_sync(0xffffffffu, u, j + 0);
            int u1 = __shfl_sync(0xffffffffu, u, j + 1);
            float c0 = __shfl_sync(0xffffffffu, su, j + 0);
            float c1 = __shfl_sync(0xffffffffu, su, j + 1);
            if (act) {
                float4 r0 = *(const float4*)(g_h2 + (size_t)u0 * 40 + lane * 4);
                float4 r1 = *(const float4*)(g_h2 + (size_t)u1 * 40 + lane * 4);
                acc.x = fmaf(c0, r0.x, acc.x); acc.y = fmaf(c0, r0.y, acc.y);
                acc.z = fmaf(c0, r0.z, acc.z); acc.w = fmaf(c0, r0.w, acc.w);
                acc.x = fmaf(c1, r1.x, acc.x); acc.y = fmaf(c1, r1.y, acc.y);
                acc.z = fmaf(c1, r1.z, acc.z); acc.w = fmaf(c1, r1.w, acc.w);
            }
        }
        for (; j < cnt; j++) {
            int uj = __shfl_sync(0xffffffffu, u, j);
            float sj = __shfl_sync(0xffffffffu, su, j);
            if (act) {
                float4 r = *(const float4*)(g_h2 + (size_t)uj * 40 + lane * 4);
                acc.x = fmaf(sj, r.x, acc.x);
                acc.y = fmaf(sj, r.y, acc.y);
                acc.z = fmaf(sj, r.z, acc.z);
                acc.w = fmaf(sj, r.w, acc.w);
            }
        }
    }
    if (act) {
        float4 bv = *(const float4*)(bias + lane * 4);
        float4 out;
        out.x = fmaf(dv, acc.x, bv.x);
        out.y = fmaf(dv, acc.y, bv.y);
        out.z = fmaf(dv, acc.z, bv.z);
        out.w = fmaf(dv, acc.w, bv.w);
        *(float4*)(O + (size_t)v * 40 + lane * 4) = out;
    }
}

// ---------------- launch -----------------------------------------------------
extern "C" void kernel_launch(void* const* d_in, const int* in_sizes, int n_in,
                              void* d_out, int out_size) {
    const float* x  = (const float*)d_in[0];
    const int*   ei = (const int*)d_in[1];
    const float* W0 = (const float*)d_in[2];
    const float* b0 = (const float*)d_in[3];
    const float* W1 = (const float*)d_in[4];
    const float* b1 = (const float*)d_in[5];
    const float* W2 = (const float*)d_in[6];
    const float* b2 = (const float*)d_in[7];
    float* out = (float*)d_out;

    int N = in_sizes[0] / 128;
    int E = in_sizes[1] / 2;
    const int* src = ei;
    const int* dst = ei + E;

    // --- CSR build + degrees ---
    k_zero   <<<(N + 255) / 256, 256>>>(N);
    k_count  <<<(E + 255) / 256, 256>>>(dst, E);
    k_dinv   <<<(N + 255) / 256, 256>>>(N);
    int nb = (N + SCAN_CH - 1) / SCAN_CH;
    k_scan1  <<<nb, SCAN_CH>>>(N);
    k_scan2  <<<1, NBMAX>>>(nb);
    k_scan3  <<<(N + 255) / 256, 256>>>(N, E);
    k_scatter<<<(E + 255) / 256, 256>>>(src, dst, E);

    int gb = (N + 127) / 128;
    int ab = (N + 7) / 8;

    // layer 0: x @ W0 -> h0 ; agg(h0) + b0, relu -> h1
    k_gemm128<<<gb, 256>>>(x, -1, W0, 0, N);
    k_agg128 <<<ab, 256>>>(0, 1, b0, 1, N);
    // layer 1: h1 @ W1 -> h0 ; agg(h0) + b1, relu -> h1
    k_gemm128<<<gb, 256>>>(nullptr, 1, W1, 0, N);
    k_agg128 <<<ab, 256>>>(0, 1, b1, 1, N);
    // layer 2: h1 @ W2 -> h2 ; agg(h2) + b2 -> out
    k_gemm40 <<<gb, 128>>>(W2, N);
    k_agg40  <<<ab, 256>>>(out, b2, N);
}